// round 7
// baseline (speedup 1.0000x reference)
#include <cuda_runtime.h>
#include <cuda_fp16.h>

#define BATCH   128
#define NUM_IN  4096
#define NLEV    8
#define H       32768
#define KFAN    32
#define NOUT    256
#define KOUT    64
#define SCALE   4.9f

#define NODES   (NUM_IN + NLEV * H)   // 266240 nodes, node-major

// Node-major activation buffer in fp16: buf[node * BATCH + b].  ~65 MB scratch.
__device__ __align__(256) __half g_buf[(size_t)NODES * BATCH];

// Monotonic ticket barrier counter. Never reset: replay-safe because every
// block arrives exactly once per phase, so phase r occupies tickets
// [r*G, (r+1)*G) globally across all launches/replays.
__device__ unsigned g_bar = 0u;

__device__ __forceinline__ float fast_sigmoid(float x) {
    return 1.0f / (1.0f + __expf(-x));
}

__device__ __forceinline__ void grid_barrier(unsigned G) {
    __syncthreads();
    if (threadIdx.x == 0) {
        __threadfence();                      // release: publish our writes
        const unsigned t = atomicAdd(&g_bar, 1u);
        const unsigned target = (t / G + 1u) * G;
        while (*(volatile unsigned*)&g_bar < target) { /* spin (L2 poll) */ }
        __threadfence();                      // acquire
    }
    __syncthreads();
}

// Convert a gathered uint2 (4 halves) and FMA into a float accumulator quad.
__device__ __forceinline__ void fma4(const uint2 v, const float wv,
                                     float& x, float& y, float& z, float& w_) {
    const float2 f01 = __half22float2(*(const __half2*)&v.x);
    const float2 f23 = __half22float2(*(const __half2*)&v.y);
    x  = fmaf(wv, f01.x, x);
    y  = fmaf(wv, f01.y, y);
    z  = fmaf(wv, f23.x, z);
    w_ = fmaf(wv, f23.y, w_);
}

// ---------------------------------------------------------------------------
// ONE persistent kernel: input transpose -> 8 levels -> output, separated by
// software grid barriers. One warp per unit; lane owns a batch quad.
// ---------------------------------------------------------------------------
__global__ void __launch_bounds__(256, 3) fused_kernel(
    const float* __restrict__ x,          // [B, NUM_IN]
    const float* __restrict__ w_hidden,   // [L, H, K]
    const int*   __restrict__ idx_hidden, // [L, H, K]
    const float* __restrict__ w_out,      // [O, KO]
    const int*   __restrict__ idx_out,    // [O, KO]
    float*       __restrict__ out,        // [B, O]
    int nblocks)
{
    const unsigned G = (unsigned)nblocks;
    const int lane   = threadIdx.x & 31;        // batch quad 4*lane..4*lane+3
    const int gw     = blockIdx.x * 8 + (threadIdx.x >> 5);
    const int nwarps = nblocks * 8;

    const uint2* __restrict__ buf2 = (const uint2*)g_buf;   // node*32 + lane

    // ---- Phase 0: transpose + quantize inputs (tiny: 4096 nodes) ----
    for (int n = gw; n < NUM_IN; n += nwarps) {
        const int b0 = lane * 4;
        const float v0 = __ldg(&x[(size_t)(b0 + 0) * NUM_IN + n]);
        const float v1 = __ldg(&x[(size_t)(b0 + 1) * NUM_IN + n]);
        const float v2 = __ldg(&x[(size_t)(b0 + 2) * NUM_IN + n]);
        const float v3 = __ldg(&x[(size_t)(b0 + 3) * NUM_IN + n]);
        const __half2 h01 = __floats2half2_rn(v0, v1);
        const __half2 h23 = __floats2half2_rn(v2, v3);
        uint2 p;
        p.x = *(const unsigned int*)&h01;
        p.y = *(const unsigned int*)&h23;
        *(uint2*)(g_buf + (size_t)n * BATCH + b0) = p;
    }
    grid_barrier(G);

    // ---- Phases 1..8: hidden levels ----
    for (int l = 0; l < NLEV; ++l) {
        const int base = NUM_IN + l * H;
        const float* __restrict__ wl = w_hidden   + (size_t)l * H * KFAN;
        const int*   __restrict__ il = idx_hidden + (size_t)l * H * KFAN;

        for (int u = gw; u < H; u += nwarps) {
            const int4*   ip4 = (const int4*)  (il + (size_t)u * KFAN);
            const float4* wp4 = (const float4*)(wl + (size_t)u * KFAN);

            float ax = 0.f, ay = 0.f, az = 0.f, aw = 0.f;   // stream A
            float bx = 0.f, by = 0.f, bz = 0.f, bw = 0.f;   // stream B

#pragma unroll
            for (int kk = 0; kk < KFAN / 8; ++kk) {
                const int4 iA = __ldg(ip4 + kk);
                const int4 iB = __ldg(ip4 + kk + 4);

                // 8 independent gathers issued back-to-back.
                const uint2 vA0 = __ldg(buf2 + (size_t)iA.x * 32 + lane);
                const uint2 vA1 = __ldg(buf2 + (size_t)iA.y * 32 + lane);
                const uint2 vA2 = __ldg(buf2 + (size_t)iA.z * 32 + lane);
                const uint2 vA3 = __ldg(buf2 + (size_t)iA.w * 32 + lane);
                const uint2 vB0 = __ldg(buf2 + (size_t)iB.x * 32 + lane);
                const uint2 vB1 = __ldg(buf2 + (size_t)iB.y * 32 + lane);
                const uint2 vB2 = __ldg(buf2 + (size_t)iB.z * 32 + lane);
                const uint2 vB3 = __ldg(buf2 + (size_t)iB.w * 32 + lane);

                const float4 wA = __ldg(wp4 + kk);
                const float4 wB = __ldg(wp4 + kk + 4);

                fma4(vA0, wA.x, ax, ay, az, aw);
                fma4(vA1, wA.y, ax, ay, az, aw);
                fma4(vA2, wA.z, ax, ay, az, aw);
                fma4(vA3, wA.w, ax, ay, az, aw);

                fma4(vB0, wB.x, bx, by, bz, bw);
                fma4(vB1, wB.y, bx, by, bz, bw);
                fma4(vB2, wB.z, bx, by, bz, bw);
                fma4(vB3, wB.w, bx, by, bz, bw);
            }

            const __half2 r01 = __floats2half2_rn(fast_sigmoid(SCALE * (ax + bx)),
                                                  fast_sigmoid(SCALE * (ay + by)));
            const __half2 r23 = __floats2half2_rn(fast_sigmoid(SCALE * (az + bz)),
                                                  fast_sigmoid(SCALE * (aw + bw)));
            uint2 packed;
            packed.x = *(const unsigned int*)&r01;
            packed.y = *(const unsigned int*)&r23;
            *(uint2*)(g_buf + (size_t)(base + u) * BATCH + lane * 4) = packed;
        }
        grid_barrier(G);
    }

    // ---- Phase 9: output layer (256 units; extra warps just exit) ----
    for (int o = gw; o < NOUT; o += nwarps) {
        const int4*   ip4 = (const int4*)  (idx_out + (size_t)o * KOUT);
        const float4* wp4 = (const float4*)(w_out   + (size_t)o * KOUT);

        float ax = 0.f, ay = 0.f, az = 0.f, aw = 0.f;

#pragma unroll
        for (int kk = 0; kk < KOUT / 4; ++kk) {
            const int4   i4 = __ldg(ip4 + kk);
            const float4 w4 = __ldg(wp4 + kk);

            const uint2 v0 = __ldg(buf2 + (size_t)i4.x * 32 + lane);
            const uint2 v1 = __ldg(buf2 + (size_t)i4.y * 32 + lane);
            const uint2 v2 = __ldg(buf2 + (size_t)i4.z * 32 + lane);
            const uint2 v3 = __ldg(buf2 + (size_t)i4.w * 32 + lane);

            fma4(v0, w4.x, ax, ay, az, aw);
            fma4(v1, w4.y, ax, ay, az, aw);
            fma4(v2, w4.z, ax, ay, az, aw);
            fma4(v3, w4.w, ax, ay, az, aw);
        }

        const int b0 = lane * 4;
        out[(size_t)(b0 + 0) * NOUT + o] = fast_sigmoid(SCALE * ax);
        out[(size_t)(b0 + 1) * NOUT + o] = fast_sigmoid(SCALE * ay);
        out[(size_t)(b0 + 2) * NOUT + o] = fast_sigmoid(SCALE * az);
        out[(size_t)(b0 + 3) * NOUT + o] = fast_sigmoid(SCALE * aw);
    }
}

// ---------------------------------------------------------------------------
// Launch: ONE persistent kernel. Grid sized so all blocks are co-resident
// (occupancy query x SM count) -- required for the software grid barrier.
// ---------------------------------------------------------------------------
extern "C" void kernel_launch(void* const* d_in, const int* in_sizes, int n_in,
                              void* d_out, int out_size) {
    const float* x        = (const float*)d_in[0];
    const float* w_hidden = (const float*)d_in[1];  // [L, H, K]
    const float* w_out    = (const float*)d_in[2];  // [O, KO]
    const int*   idx_hid  = (const int*)  d_in[3];  // [L, H, K]
    const int*   idx_out  = (const int*)  d_in[4];  // [O, KO]
    float*       out      = (float*)d_out;          // [B, O]

    int dev = 0;
    cudaGetDevice(&dev);
    int sms = 0;
    cudaDeviceGetAttribute(&sms, cudaDevAttrMultiProcessorCount, dev);
    int nb = 0;
    cudaOccupancyMaxActiveBlocksPerMultiprocessor(&nb, fused_kernel, 256, 0);
    if (sms <= 0) sms = 148;
    if (nb  <= 0) nb  = 1;

    const int nblocks = sms * nb;   // all guaranteed co-resident

    fused_kernel<<<nblocks, 256>>>(x, w_hidden, idx_hid, w_out, idx_out,
                                   out, nblocks);
}